// round 1
// baseline (speedup 1.0000x reference)
#include <cuda_runtime.h>
#include <cstdint>

#define N_DIM   16384
#define F_DIM   32
#define BM      128
#define BK      32
#define NTHREADS 128
#define AS_STRIDE 130        // 2-way STS conflict, conflict-free compute LDS
#define NTILES  (N_DIM / BK) // 512

// Scratch (allocation-free rule: __device__ globals)
__device__ __align__(16) float g_x[N_DIM * F_DIM];  // features @ W
__device__ __align__(16) float g_y[N_DIM * F_DIM];  // diag * (Winv @ x)

// ---------- packed f32x2 helpers (Blackwell FFMA2 path) ----------
__device__ __forceinline__ unsigned long long ffma2(unsigned long long a,
                                                    unsigned long long b,
                                                    unsigned long long c) {
    unsigned long long d;
    asm("fma.rn.f32x2 %0, %1, %2, %3;" : "=l"(d) : "l"(a), "l"(b), "l"(c));
    return d;
}
__device__ __forceinline__ unsigned long long fmul2(unsigned long long a,
                                                    unsigned long long b) {
    unsigned long long d;
    asm("mul.rn.f32x2 %0, %1, %2;" : "=l"(d) : "l"(a), "l"(b));
    return d;
}
__device__ __forceinline__ unsigned long long dup2(float x) {
    unsigned long long d;
    asm("mov.b64 %0, {%1, %2};" : "=l"(d) : "f"(x), "f"(x));
    return d;
}

// ---------- tiny GEMM: g_x = features[N,32] @ W[32,32] ----------
__global__ void feat_w_kernel(const float* __restrict__ feat,
                              const float* __restrict__ W) {
    __shared__ float sW[F_DIM * F_DIM];
    int tid = threadIdx.x;
    for (int i = tid; i < F_DIM * F_DIM; i += NTHREADS) sW[i] = W[i];
    __syncthreads();

    int row = blockIdx.x * NTHREADS + tid;
    float f[F_DIM];
    const float4* fr = reinterpret_cast<const float4*>(feat + (size_t)row * F_DIM);
#pragma unroll
    for (int i = 0; i < F_DIM / 4; i++) {
        float4 v = fr[i];
        f[4*i+0] = v.x; f[4*i+1] = v.y; f[4*i+2] = v.z; f[4*i+3] = v.w;
    }
#pragma unroll 4
    for (int c = 0; c < F_DIM; c++) {
        float acc = 0.f;
#pragma unroll
        for (int k = 0; k < F_DIM; k++) acc = fmaf(f[k], sW[k * F_DIM + c], acc);
        g_x[(size_t)row * F_DIM + c] = acc;
    }
}

// ---------- big GEMM: out[r][c] = (scale?) * sum_k A[r][k] * B[k][c] ----------
// MODE 1: B = g_x, row-scale = diag, out = g_y
// MODE 2: B = g_y, no scale,        out = out_param
template <int MODE>
__global__ __launch_bounds__(NTHREADS)
void big_gemm_kernel(const float* __restrict__ A,
                     const float* __restrict__ scale,
                     float* __restrict__ out_param) {
    const float* __restrict__ Bm = (MODE == 1) ? g_x : g_y;
    float* outm = (MODE == 1) ? g_y : out_param;

    __shared__ float As[2][BK * AS_STRIDE];
    __shared__ float Bs[2][BK * F_DIM];

    const int tid  = threadIdx.x;
    const int lane = tid & 31;
    const int warp = tid >> 5;      // col group: cols warp*8 .. warp*8+7
    const int row0 = blockIdx.x * BM;
    const int rsub = tid >> 3;      // 0..15
    const int k4   = tid & 7;       // 0..7

    float4 areg[8];
    float4 breg[2];

    auto ldg_tile = [&](int t) {
        const float* Ab = A + (size_t)row0 * N_DIM + (size_t)t * BK;
#pragma unroll
        for (int i = 0; i < 8; i++) {
            int r = i * 16 + rsub;
            areg[i] = *reinterpret_cast<const float4*>(Ab + (size_t)r * N_DIM + k4 * 4);
        }
        const float4* Bb = reinterpret_cast<const float4*>(Bm + (size_t)t * BK * F_DIM);
        breg[0] = Bb[tid];
        breg[1] = Bb[tid + 128];
    };
    auto sts_tile = [&](int buf) {
        float* dst = &As[buf][0];
#pragma unroll
        for (int i = 0; i < 8; i++) {
            int r = i * 16 + rsub;
            dst[(k4 * 4 + 0) * AS_STRIDE + r] = areg[i].x;
            dst[(k4 * 4 + 1) * AS_STRIDE + r] = areg[i].y;
            dst[(k4 * 4 + 2) * AS_STRIDE + r] = areg[i].z;
            dst[(k4 * 4 + 3) * AS_STRIDE + r] = areg[i].w;
        }
        float4* bd = reinterpret_cast<float4*>(&Bs[buf][0]);
        bd[tid]       = breg[0];
        bd[tid + 128] = breg[1];
    };

    unsigned long long acc[4][4];
#pragma unroll
    for (int i = 0; i < 4; i++)
#pragma unroll
        for (int j = 0; j < 4; j++) acc[i][j] = 0ull;

    // prologue: fill buf0, prefetch tile 1 into regs
    ldg_tile(0);
    sts_tile(0);
    ldg_tile(1);
    __syncthreads();

    for (int t = 0; t < NTILES; t++) {
        const int cur = t & 1;
        if (t + 1 < NTILES) sts_tile(cur ^ 1);   // overlaps with compute(t)
        if (t + 2 < NTILES) ldg_tile(t + 2);     // lands during compute(t)

        const float* as = &As[cur][0];
        const float* bs = &Bs[cur][0];
#pragma unroll
        for (int kk = 0; kk < BK; kk++) {
            const float* ar = as + kk * AS_STRIDE + lane;
            float a0 = ar[0];
            float a1 = ar[32];
            float a2 = ar[64];
            float a3 = ar[96];
            const ulonglong2* bp =
                reinterpret_cast<const ulonglong2*>(bs + kk * F_DIM + warp * 8);
            ulonglong2 b01 = bp[0];  // smem broadcast (all lanes same addr)
            ulonglong2 b23 = bp[1];

            unsigned long long ad;
            ad = dup2(a0);
            acc[0][0] = ffma2(ad, b01.x, acc[0][0]);
            acc[0][1] = ffma2(ad, b01.y, acc[0][1]);
            acc[0][2] = ffma2(ad, b23.x, acc[0][2]);
            acc[0][3] = ffma2(ad, b23.y, acc[0][3]);
            ad = dup2(a1);
            acc[1][0] = ffma2(ad, b01.x, acc[1][0]);
            acc[1][1] = ffma2(ad, b01.y, acc[1][1]);
            acc[1][2] = ffma2(ad, b23.x, acc[1][2]);
            acc[1][3] = ffma2(ad, b23.y, acc[1][3]);
            ad = dup2(a2);
            acc[2][0] = ffma2(ad, b01.x, acc[2][0]);
            acc[2][1] = ffma2(ad, b01.y, acc[2][1]);
            acc[2][2] = ffma2(ad, b23.x, acc[2][2]);
            acc[2][3] = ffma2(ad, b23.y, acc[2][3]);
            ad = dup2(a3);
            acc[3][0] = ffma2(ad, b01.x, acc[3][0]);
            acc[3][1] = ffma2(ad, b01.y, acc[3][1]);
            acc[3][2] = ffma2(ad, b23.x, acc[3][2]);
            acc[3][3] = ffma2(ad, b23.y, acc[3][3]);
        }
        __syncthreads();
    }

    // epilogue: optional row scale, 8B packed stores
#pragma unroll
    for (int i = 0; i < 4; i++) {
        int row = row0 + lane + 32 * i;
        unsigned long long s2 = 0ull;
        if (MODE == 1) s2 = dup2(scale[row]);
        unsigned long long* op =
            reinterpret_cast<unsigned long long*>(outm + (size_t)row * F_DIM + warp * 8);
#pragma unroll
        for (int j = 0; j < 4; j++) {
            unsigned long long v = acc[i][j];
            if (MODE == 1) v = fmul2(v, s2);
            op[j] = v;
        }
    }
}

extern "C" void kernel_launch(void* const* d_in, const int* in_sizes, int n_in,
                              void* d_out, int out_size) {
    const float* feat = (const float*)d_in[0];  // [16384, 32]
    const float* wav  = (const float*)d_in[1];  // [16384, 16384]
    const float* wavi = (const float*)d_in[2];  // [16384, 16384]
    const float* diag = (const float*)d_in[3];  // [16384]
    const float* Wm   = (const float*)d_in[4];  // [32, 32]
    float* out = (float*)d_out;                 // [16384, 32]

    feat_w_kernel<<<N_DIM / NTHREADS, NTHREADS>>>(feat, Wm);
    big_gemm_kernel<1><<<N_DIM / BM, NTHREADS>>>(wavi, diag, nullptr);
    big_gemm_kernel<2><<<N_DIM / BM, NTHREADS>>>(wav, nullptr, out);
}

// round 4
// speedup vs baseline: 1.7955x; 1.7955x over previous
#include <cuda_runtime.h>
#include <cstdint>

#define N_DIM   16384
#define F_DIM   32
#define BM      128
#define BK      64
#define NTILES  (N_DIM / BK)   // 256
#define THREADS 256
#define PAD_ROW 72             // bf16 elems per smem row (64 + 8 pad)
#define ROWB    (PAD_ROW * 2)  // 144 bytes

// smem layout (bytes, per stage)
#define AH_OFF  0
#define AL_OFF  (BM * ROWB)                // 18432
#define BH_OFF  (2 * BM * ROWB)            // 36864
#define BL_OFF  (2 * BM * ROWB + F_DIM * ROWB)   // 41472
#define STAGE_B (2 * BM * ROWB + 2 * F_DIM * ROWB) // 46080
#define SMEM_TOTAL (2 * STAGE_B)           // 92160

__device__ __align__(16) float g_xT[F_DIM * N_DIM];  // (features@W)^T   [32][16384]
__device__ __align__(16) float g_yT[F_DIM * N_DIM];  // (diag*(Winv@x))^T

// ---------------- helpers ----------------
__device__ __forceinline__ uint32_t smem_u32(const void* p) {
    uint32_t a;
    asm("{ .reg .u64 t; cvta.to.shared.u64 t, %1; cvt.u32.u64 %0, t; }" : "=r"(a) : "l"(p));
    return a;
}
__device__ __forceinline__ void ldsm4(uint32_t* r, uint32_t addr) {
    asm volatile("ldmatrix.sync.aligned.m8n8.x4.shared.b16 {%0,%1,%2,%3}, [%4];"
                 : "=r"(r[0]), "=r"(r[1]), "=r"(r[2]), "=r"(r[3]) : "r"(addr));
}
__device__ __forceinline__ uint32_t lds32(uint32_t addr) {
    uint32_t v;
    asm volatile("ld.shared.b32 %0, [%1];" : "=r"(v) : "r"(addr));
    return v;
}
__device__ __forceinline__ void mma_bf16(float* c, const uint32_t* a, uint32_t b0, uint32_t b1) {
    asm volatile("mma.sync.aligned.m16n8k16.row.col.f32.bf16.bf16.f32 "
                 "{%0,%1,%2,%3}, {%4,%5,%6,%7}, {%8,%9}, {%0,%1,%2,%3};"
                 : "+f"(c[0]), "+f"(c[1]), "+f"(c[2]), "+f"(c[3])
                 : "r"(a[0]), "r"(a[1]), "r"(a[2]), "r"(a[3]), "r"(b0), "r"(b1));
}
// RN round-to-bf16 of x, returned as fp32 bits (low 16 zero)
__device__ __forceinline__ uint32_t bf16_hi_bits(float x) {
    uint32_t u = __float_as_uint(x);
    return (u + 0x7FFFu + ((u >> 16) & 1u)) & 0xFFFF0000u;
}
__device__ __forceinline__ uint32_t pack_bf16_rn(float lo, float hi) {
    uint32_t r;
    asm("cvt.rn.bf16x2.f32 %0, %1, %2;" : "=r"(r) : "f"(hi), "f"(lo));
    return r;
}
// split float4 -> bf16 hi tile + bf16 lo tile (8B each), store
__device__ __forceinline__ void split_store(float4 v, uint32_t a_hi, uint32_t a_lo) {
    uint32_t h0 = bf16_hi_bits(v.x), h1 = bf16_hi_bits(v.y);
    uint32_t h2 = bf16_hi_bits(v.z), h3 = bf16_hi_bits(v.w);
    float l0 = v.x - __uint_as_float(h0), l1 = v.y - __uint_as_float(h1);
    float l2 = v.z - __uint_as_float(h2), l3 = v.w - __uint_as_float(h3);
    uint32_t ph0 = (h0 >> 16) | (h1 & 0xFFFF0000u);
    uint32_t ph1 = (h2 >> 16) | (h3 & 0xFFFF0000u);
    uint32_t pl0 = pack_bf16_rn(l0, l1);
    uint32_t pl1 = pack_bf16_rn(l2, l3);
    asm volatile("st.shared.v2.b32 [%0], {%1,%2};" :: "r"(a_hi), "r"(ph0), "r"(ph1) : "memory");
    asm volatile("st.shared.v2.b32 [%0], {%1,%2};" :: "r"(a_lo), "r"(pl0), "r"(pl1) : "memory");
}

// ---------- prep: g_xT[c][row] = (features @ W)[row][c] ----------
__global__ void feat_w_kernel(const float* __restrict__ feat,
                              const float* __restrict__ W) {
    __shared__ float sW[F_DIM * F_DIM];
    int tid = threadIdx.x;
    for (int i = tid; i < F_DIM * F_DIM; i += 128) sW[i] = W[i];
    __syncthreads();
    int row = blockIdx.x * 128 + tid;
    float f[F_DIM];
    const float4* fr = reinterpret_cast<const float4*>(feat + (size_t)row * F_DIM);
#pragma unroll
    for (int i = 0; i < 8; i++) {
        float4 v = fr[i];
        f[4*i] = v.x; f[4*i+1] = v.y; f[4*i+2] = v.z; f[4*i+3] = v.w;
    }
#pragma unroll 4
    for (int c = 0; c < F_DIM; c++) {
        float acc = 0.f;
#pragma unroll
        for (int k = 0; k < F_DIM; k++) acc = fmaf(f[k], sW[k * F_DIM + c], acc);
        g_xT[(size_t)c * N_DIM + row] = acc;
    }
}

// ---------- big GEMM: D[r][c] = sum_k A[r][k] * Bt[c][k]  (bf16x2 3-pass) ----------
// MODE 1: Bt=g_xT (device symbol), out -> g_yT (transposed) with diag row scale
// MODE 2: Bt=g_yT (device symbol), out -> row-major out_param
template <int MODE>
__global__ __launch_bounds__(THREADS, 1)
void big_gemm_mma(const float* __restrict__ A,
                  const float* __restrict__ diag,
                  float* __restrict__ out_param) {
    // CRITICAL: device-side symbol reference (host-passed __device__ ptr is UB)
    const float* __restrict__ Bt = (MODE == 1) ? g_xT : g_yT;

    extern __shared__ char smem[];
    const uint32_t sb = smem_u32(smem);
    const int tid  = threadIdx.x;
    const int lane = tid & 31;
    const int w    = tid >> 5;        // 8 warps, warp w -> rows w*16..w*16+15
    const int row0 = blockIdx.x * BM;

    // ---- producer addressing ----
    const float4* ap[8];
    uint32_t sA[8];
#pragma unroll
    for (int i = 0; i < 8; i++) {
        int chunk = tid + THREADS * i;          // 0..2047
        int row = chunk >> 4, c4 = chunk & 15;
        ap[i] = reinterpret_cast<const float4*>(A + (size_t)(row0 + row) * N_DIM) + c4;
        sA[i] = (uint32_t)(row * ROWB + c4 * 8);
    }
    const float4* bp[2];
    uint32_t sB[2];
#pragma unroll
    for (int j = 0; j < 2; j++) {
        int chunk = tid + THREADS * j;          // 0..511
        int n = chunk >> 4, c4 = chunk & 15;
        bp[j] = reinterpret_cast<const float4*>(Bt + (size_t)n * N_DIM) + c4;
        sB[j] = (uint32_t)(n * ROWB + c4 * 8);
    }

    float4 ra[8], rb[2];
    auto ldg = [&](int t) {
        const int o = t * (BK / 4);
#pragma unroll
        for (int i = 0; i < 8; i++) ra[i] = __ldg(ap[i] + o);
#pragma unroll
        for (int j = 0; j < 2; j++) rb[j] = __ldg(bp[j] + o);
    };
    auto sts = [&](int buf) {
        const uint32_t base = sb + buf * STAGE_B;
#pragma unroll
        for (int i = 0; i < 8; i++)
            split_store(ra[i], base + AH_OFF + sA[i], base + AL_OFF + sA[i]);
#pragma unroll
        for (int j = 0; j < 2; j++)
            split_store(rb[j], base + BH_OFF + sB[j], base + BL_OFF + sB[j]);
    };

    // ---- consumer addressing ----
    // A fragment ldmatrix: rows w*16 + (lane&15), col byte = (lane>>4)*16 (+kk*32)
    const uint32_t aoff = (uint32_t)((w * 16 + (lane & 15)) * ROWB + (lane >> 4) * 16);
    // B fragment: n = lane/4, k byte = (lane&3)*4 (+kk*32), second reg +16
    const uint32_t boff = (uint32_t)((lane >> 2) * ROWB + (lane & 3) * 4);

    float acc[4][4];
#pragma unroll
    for (int j = 0; j < 4; j++)
#pragma unroll
        for (int i = 0; i < 4; i++) acc[j][i] = 0.f;

    ldg(0); sts(0); ldg(1);
    __syncthreads();

    for (int t = 0; t < NTILES; t++) {
        const int cur = t & 1;
        if (t + 1 < NTILES) sts(cur ^ 1);
        if (t + 2 < NTILES) ldg(t + 2);

        const uint32_t tb = sb + cur * STAGE_B;
        const uint32_t aH = tb + AH_OFF + aoff;
        const uint32_t aL = tb + AL_OFF + aoff;
        const uint32_t bH = tb + BH_OFF + boff;
#pragma unroll
        for (int kk = 0; kk < 4; kk++) {
            uint32_t ah[4], al[4];
            ldsm4(ah, aH + kk * 32);
            ldsm4(al, aL + kk * 32);
#pragma unroll
            for (int j = 0; j < 4; j++) {
                const uint32_t bo = bH + (uint32_t)(j * 8 * ROWB) + kk * 32;
                uint32_t bh0 = lds32(bo);
                uint32_t bh1 = lds32(bo + 16);
                uint32_t bl0 = lds32(bo + (BL_OFF - BH_OFF));
                uint32_t bl1 = lds32(bo + (BL_OFF - BH_OFF) + 16);
                mma_bf16(acc[j], ah, bh0, bh1);   // Ah*Bh
                mma_bf16(acc[j], al, bh0, bh1);   // Al*Bh
                mma_bf16(acc[j], ah, bl0, bl1);   // Ah*Bl
            }
        }
        __syncthreads();
    }

    // ---- epilogue: c-frag (row = lane/4 [+8], col = (lane&3)*2 [+1]) ----
    const int ra0 = row0 + w * 16 + (lane >> 2);
    const int ra1 = ra0 + 8;
    if (MODE == 1) {
        const float s0 = diag[ra0];
        const float s1 = diag[ra1];
#pragma unroll
        for (int j = 0; j < 4; j++) {
            const int c = j * 8 + (lane & 3) * 2;
            g_yT[(size_t)c       * N_DIM + ra0] = acc[j][0] * s0;
            g_yT[(size_t)(c + 1) * N_DIM + ra0] = acc[j][1] * s0;
            g_yT[(size_t)c       * N_DIM + ra1] = acc[j][2] * s1;
            g_yT[(size_t)(c + 1) * N_DIM + ra1] = acc[j][3] * s1;
        }
    } else {
#pragma unroll
        for (int j = 0; j < 4; j++) {
            const int c = j * 8 + (lane & 3) * 2;
            *reinterpret_cast<float2*>(out_param + (size_t)ra0 * F_DIM + c) =
                make_float2(acc[j][0], acc[j][1]);
            *reinterpret_cast<float2*>(out_param + (size_t)ra1 * F_DIM + c) =
                make_float2(acc[j][2], acc[j][3]);
        }
    }
}

extern "C" void kernel_launch(void* const* d_in, const int* in_sizes, int n_in,
                              void* d_out, int out_size) {
    const float* feat = (const float*)d_in[0];  // [16384, 32]
    const float* wav  = (const float*)d_in[1];  // [16384, 16384]
    const float* wavi = (const float*)d_in[2];  // [16384, 16384]
    const float* diag = (const float*)d_in[3];  // [16384]
    const float* Wm   = (const float*)d_in[4];  // [32, 32]
    float* out = (float*)d_out;

    cudaFuncSetAttribute(big_gemm_mma<1>, cudaFuncAttributeMaxDynamicSharedMemorySize, SMEM_TOTAL);
    cudaFuncSetAttribute(big_gemm_mma<2>, cudaFuncAttributeMaxDynamicSharedMemorySize, SMEM_TOTAL);

    feat_w_kernel<<<N_DIM / 128, 128>>>(feat, Wm);
    big_gemm_mma<1><<<N_DIM / BM, THREADS, SMEM_TOTAL>>>(wavi, diag, nullptr);
    big_gemm_mma<2><<<N_DIM / BM, THREADS, SMEM_TOTAL>>>(wav, nullptr, out);
}

// round 5
// speedup vs baseline: 2.3280x; 1.2965x over previous
#include <cuda_runtime.h>
#include <cuda_bf16.h>
#include <cstdint>

#define N_DIM   16384
#define F_DIM   32
#define BM      128
#define BK      64
#define NTILES  (N_DIM / BK)   // 256
#define THREADS 256
#define ROWB    144            // B bf16 smem row stride bytes (64*2 + 16 pad)

// ---- smem stage layout ----
#define STAGE_A_SZ 32768       // 128 rows x 64 f32 (256B/row, xor-swizzled)
#define BH_SZ      4608        // 32 rows x 144B
#define STAGE_SZ   (STAGE_A_SZ + 2 * BH_SZ)   // 41984
#define NSTAGE     4
#define SMEM_TOTAL (NSTAGE * STAGE_SZ)        // 167936

// pre-split B operands (bf16 hi/lo), [F_DIM][N_DIM] transposed layout
__device__ __align__(16) __nv_bfloat16 g_bh1[F_DIM * N_DIM];
__device__ __align__(16) __nv_bfloat16 g_bl1[F_DIM * N_DIM];
__device__ __align__(16) __nv_bfloat16 g_bh2[F_DIM * N_DIM];
__device__ __align__(16) __nv_bfloat16 g_bl2[F_DIM * N_DIM];

// ---------------- helpers ----------------
__device__ __forceinline__ uint32_t smem_u32(const void* p) {
    uint32_t a;
    asm("{ .reg .u64 t; cvta.to.shared.u64 t, %1; cvt.u32.u64 %0, t; }" : "=r"(a) : "l"(p));
    return a;
}
#define CP_ASYNC16(dst, src) \
    asm volatile("cp.async.cg.shared.global [%0], [%1], 16;" :: "r"(dst), "l"(src) : "memory")
#define CP_COMMIT()  asm volatile("cp.async.commit_group;" ::: "memory")
#define CP_WAIT2()   asm volatile("cp.async.wait_group 2;" ::: "memory")

__device__ __forceinline__ float2 lds_f2(uint32_t a) {
    float2 v;
    asm volatile("ld.shared.v2.f32 {%0,%1}, [%2];" : "=f"(v.x), "=f"(v.y) : "r"(a));
    return v;
}
__device__ __forceinline__ uint32_t lds32(uint32_t addr) {
    uint32_t v;
    asm volatile("ld.shared.b32 %0, [%1];" : "=r"(v) : "r"(addr));
    return v;
}
__device__ __forceinline__ void mma_bf16(float* c, const uint32_t* a, uint32_t b0, uint32_t b1) {
    asm volatile("mma.sync.aligned.m16n8k16.row.col.f32.bf16.bf16.f32 "
                 "{%0,%1,%2,%3}, {%4,%5,%6,%7}, {%8,%9}, {%0,%1,%2,%3};"
                 : "+f"(c[0]), "+f"(c[1]), "+f"(c[2]), "+f"(c[3])
                 : "r"(a[0]), "r"(a[1]), "r"(a[2]), "r"(a[3]), "r"(b0), "r"(b1));
}
__device__ __forceinline__ uint32_t pack_bf16_rn(float lo, float hi) {
    uint32_t r;
    asm("cvt.rn.bf16x2.f32 %0, %1, %2;" : "=r"(r) : "f"(hi), "f"(lo));
    return r;
}
// split f32 pair -> packed bf16 hi (RNA) + packed bf16 lo (RN)
__device__ __forceinline__ uint32_t split2(float2 v, uint32_t& lo) {
    uint32_t hx = (__float_as_uint(v.x) + 0x8000u) & 0xFFFF0000u;
    uint32_t hy = (__float_as_uint(v.y) + 0x8000u) & 0xFFFF0000u;
    lo = pack_bf16_rn(v.x - __uint_as_float(hx), v.y - __uint_as_float(hy));
    return __byte_perm(hx, hy, 0x7632);
}
__device__ __forceinline__ void split_g(float v, __nv_bfloat16* ph, __nv_bfloat16* pl) {
    __nv_bfloat16 h = __float2bfloat16(v);
    *ph = h;
    *pl = __float2bfloat16(v - __bfloat162float(h));
}

// ---------- prep: split((features @ W)^T) -> g_bh1/g_bl1 ----------
__global__ void feat_w_kernel(const float* __restrict__ feat,
                              const float* __restrict__ W) {
    __shared__ float sW[F_DIM * F_DIM];
    int tid = threadIdx.x;
    for (int i = tid; i < F_DIM * F_DIM; i += 128) sW[i] = W[i];
    __syncthreads();
    int row = blockIdx.x * 128 + tid;
    float f[F_DIM];
    const float4* fr = reinterpret_cast<const float4*>(feat + (size_t)row * F_DIM);
#pragma unroll
    for (int i = 0; i < 8; i++) {
        float4 v = fr[i];
        f[4*i] = v.x; f[4*i+1] = v.y; f[4*i+2] = v.z; f[4*i+3] = v.w;
    }
#pragma unroll 4
    for (int c = 0; c < F_DIM; c++) {
        float acc = 0.f;
#pragma unroll
        for (int k = 0; k < F_DIM; k++) acc = fmaf(f[k], sW[k * F_DIM + c], acc);
        split_g(acc, &g_bh1[(size_t)c * N_DIM + row], &g_bl1[(size_t)c * N_DIM + row]);
    }
}

// ---------- big GEMM: D[r][c] = sum_k A[r][k] * B[c][k] ----------
// MODE 1: B = g_bh1/g_bl1, epilogue: diag scale, split -> g_bh2/g_bl2
// MODE 2: B = g_bh2/g_bl2, epilogue: f32 row-major out
template <int MODE>
__global__ __launch_bounds__(THREADS, 1)
void big_gemm_mma(const float* __restrict__ A,
                  const float* __restrict__ diag,
                  float* __restrict__ out_param) {
    const __nv_bfloat16* __restrict__ Bh = (MODE == 1) ? g_bh1 : g_bh2;
    const __nv_bfloat16* __restrict__ Bl = (MODE == 1) ? g_bl1 : g_bl2;

    extern __shared__ char smem[];
    const uint32_t sb = smem_u32(smem);
    const int tid  = threadIdx.x;
    const int lane = tid & 31;
    const int w    = tid >> 5;
    const int row0 = blockIdx.x * BM;

    // ---- producer: per-thread cp.async slots ----
    // A: 8 chunks of 16B; chunk = tid + 256*i -> row = chunk>>4, granule g = chunk&15
    const float* asrc[8];
    uint32_t adst[8];
#pragma unroll
    for (int i = 0; i < 8; i++) {
        int chunk = tid + THREADS * i;
        int row = chunk >> 4, g = chunk & 15;
        asrc[i] = A + (size_t)(row0 + row) * N_DIM + g * 4;
        adst[i] = (uint32_t)(row * 256 + ((g ^ ((row & 7) << 1)) << 4));
    }
    // B: 1 chunk each of bh/bl: n = tid>>3, g = tid&7
    const int bn = tid >> 3, bg = tid & 7;
    const __nv_bfloat16* bhsrc = Bh + (size_t)bn * N_DIM + bg * 8;
    const __nv_bfloat16* blsrc = Bl + (size_t)bn * N_DIM + bg * 8;
    const uint32_t bdst = (uint32_t)(STAGE_A_SZ + bn * ROWB + bg * 16);

    auto issue = [&](int t) {
        const uint32_t stg = sb + (t & 3) * STAGE_SZ;
        const int kofs = t * BK;
#pragma unroll
        for (int i = 0; i < 8; i++) CP_ASYNC16(stg + adst[i], asrc[i] + kofs);
        CP_ASYNC16(stg + bdst, bhsrc + kofs);
        CP_ASYNC16(stg + bdst + BH_SZ, blsrc + kofs);
    };

    // ---- consumer addressing ----
    const int r1 = w * 16 + (lane >> 2);            // local row (0..127)
    const uint32_t xr = (uint32_t)((r1 & 7) << 1);  // same for r1+8
    const uint32_t arow1 = (uint32_t)(r1 * 256);
    const uint32_t arow2 = arow1 + 8 * 256;
    const uint32_t gb   = (uint32_t)((lane & 3) >> 1);   // granule base from k
    const uint32_t aib  = (uint32_t)((lane & 1) * 8);    // intra-granule byte
    const uint32_t boff = (uint32_t)(STAGE_A_SZ + (lane >> 2) * ROWB + (lane & 3) * 4);

    float acc[4][4];
#pragma unroll
    for (int j = 0; j < 4; j++)
#pragma unroll
        for (int i = 0; i < 4; i++) acc[j][i] = 0.f;

    issue(0); CP_COMMIT();
    issue(1); CP_COMMIT();
    issue(2); CP_COMMIT();

    for (int t = 0; t < NTILES; t++) {
        CP_WAIT2();
        __syncthreads();
        if (t + 3 < NTILES) issue(t + 3);
        CP_COMMIT();   // empty group when past the end keeps wait_group aligned

        const uint32_t stg = sb + (t & 3) * STAGE_SZ;
#pragma unroll
        for (int kk = 0; kk < 4; kk++) {
            const uint32_t g0 = gb + (uint32_t)(kk * 4);
            const uint32_t g2 = g0 + 2;
            float2 v0 = lds_f2(stg + arow1 + ((g0 ^ xr) << 4) + aib);
            float2 v1 = lds_f2(stg + arow2 + ((g0 ^ xr) << 4) + aib);
            float2 v2 = lds_f2(stg + arow1 + ((g2 ^ xr) << 4) + aib);
            float2 v3 = lds_f2(stg + arow2 + ((g2 ^ xr) << 4) + aib);
            uint32_t ah[4], al[4];
            ah[0] = split2(v0, al[0]);
            ah[1] = split2(v1, al[1]);
            ah[2] = split2(v2, al[2]);
            ah[3] = split2(v3, al[3]);
            const uint32_t bH = stg + boff + (uint32_t)(kk * 32);
#pragma unroll
            for (int j = 0; j < 4; j++) {
                const uint32_t bo = bH + (uint32_t)(j * 8 * ROWB);
                uint32_t bh0 = lds32(bo);
                uint32_t bh1 = lds32(bo + 16);
                uint32_t bl0 = lds32(bo + BH_SZ);
                uint32_t bl1 = lds32(bo + BH_SZ + 16);
                mma_bf16(acc[j], ah, bh0, bh1);   // Ah*Bh
                mma_bf16(acc[j], al, bh0, bh1);   // Al*Bh
                mma_bf16(acc[j], ah, bl0, bl1);   // Ah*Bl
            }
        }
    }

    // ---- epilogue: c-frag rows = lane>>2 (+8), cols = j*8 + (lane&3)*2 (+1) ----
    const int gr0 = row0 + w * 16 + (lane >> 2);
    const int gr1 = gr0 + 8;
    if (MODE == 1) {
        const float s0 = diag[gr0];
        const float s1 = diag[gr1];
#pragma unroll
        for (int j = 0; j < 4; j++) {
            const int c = j * 8 + (lane & 3) * 2;
            split_g(acc[j][0] * s0, &g_bh2[(size_t)c       * N_DIM + gr0], &g_bl2[(size_t)c       * N_DIM + gr0]);
            split_g(acc[j][1] * s0, &g_bh2[(size_t)(c + 1) * N_DIM + gr0], &g_bl2[(size_t)(c + 1) * N_DIM + gr0]);
            split_g(acc[j][2] * s1, &g_bh2[(size_t)c       * N_DIM + gr1], &g_bl2[(size_t)c       * N_DIM + gr1]);
            split_g(acc[j][3] * s1, &g_bh2[(size_t)(c + 1) * N_DIM + gr1], &g_bl2[(size_t)(c + 1) * N_DIM + gr1]);
        }
    } else {
#pragma unroll
        for (int j = 0; j < 4; j++) {
            const int c = j * 8 + (lane & 3) * 2;
            *reinterpret_cast<float2*>(out_param + (size_t)gr0 * F_DIM + c) =
                make_float2(acc[j][0], acc[j][1]);
            *reinterpret_cast<float2*>(out_param + (size_t)gr1 * F_DIM + c) =
                make_float2(acc[j][2], acc[j][3]);
        }
    }
}

extern "C" void kernel_launch(void* const* d_in, const int* in_sizes, int n_in,
                              void* d_out, int out_size) {
    const float* feat = (const float*)d_in[0];  // [16384, 32]
    const float* wav  = (const float*)d_in[1];  // [16384, 16384]
    const float* wavi = (const float*)d_in[2];  // [16384, 16384]
    const float* diag = (const float*)d_in[3];  // [16384]
    const float* Wm   = (const float*)d_in[4];  // [32, 32]
    float* out = (float*)d_out;

    cudaFuncSetAttribute(big_gemm_mma<1>, cudaFuncAttributeMaxDynamicSharedMemorySize, SMEM_TOTAL);
    cudaFuncSetAttribute(big_gemm_mma<2>, cudaFuncAttributeMaxDynamicSharedMemorySize, SMEM_TOTAL);

    feat_w_kernel<<<N_DIM / 128, 128>>>(feat, Wm);
    big_gemm_mma<1><<<N_DIM / BM, THREADS, SMEM_TOTAL>>>(wavi, diag, nullptr);
    big_gemm_mma<2><<<N_DIM / BM, THREADS, SMEM_TOTAL>>>(wav, nullptr, out);
}

// round 6
// speedup vs baseline: 2.3865x; 1.0251x over previous
#include <cuda_runtime.h>
#include <cuda_bf16.h>
#include <cstdint>

#define N_DIM   16384
#define F_DIM   32
#define BM      128
#define BK      64
#define THREADS 256
#define GRID    148
#define KCHUNKS 8
#define UNIT_STAGES 32                    // stages per unit (BK each)
#define TOTAL_UNITS (128 * KCHUNKS)       // 1024
#define ROWB    144

// ---- smem stage layout ----
#define STAGE_A_SZ 32768
#define BH_SZ      4608
#define STAGE_SZ   (STAGE_A_SZ + 2 * BH_SZ)
#define NSTAGE     4
#define SMEM_TOTAL (NSTAGE * STAGE_SZ)    // 167936

// pre-split B operands (bf16 hi/lo), [F_DIM][N_DIM]
__device__ __align__(16) __nv_bfloat16 g_bh1[F_DIM * N_DIM];
__device__ __align__(16) __nv_bfloat16 g_bl1[F_DIM * N_DIM];
__device__ __align__(16) __nv_bfloat16 g_bh2[F_DIM * N_DIM];
__device__ __align__(16) __nv_bfloat16 g_bl2[F_DIM * N_DIM];
// K-split partials: [kc][row][col] f32
__device__ __align__(16) float g_part[KCHUNKS * N_DIM * F_DIM];

// ---------------- helpers ----------------
__device__ __forceinline__ uint32_t smem_u32(const void* p) {
    uint32_t a;
    asm("{ .reg .u64 t; cvta.to.shared.u64 t, %1; cvt.u32.u64 %0, t; }" : "=r"(a) : "l"(p));
    return a;
}
#define CP_ASYNC16(dst, src) \
    asm volatile("cp.async.cg.shared.global [%0], [%1], 16;" :: "r"(dst), "l"(src) : "memory")
#define CP_COMMIT()  asm volatile("cp.async.commit_group;" ::: "memory")
#define CP_WAIT2()   asm volatile("cp.async.wait_group 2;" ::: "memory")

__device__ __forceinline__ float2 lds_f2(uint32_t a) {
    float2 v;
    asm volatile("ld.shared.v2.f32 {%0,%1}, [%2];" : "=f"(v.x), "=f"(v.y) : "r"(a));
    return v;
}
__device__ __forceinline__ uint32_t lds32(uint32_t addr) {
    uint32_t v;
    asm volatile("ld.shared.b32 %0, [%1];" : "=r"(v) : "r"(addr));
    return v;
}
__device__ __forceinline__ void mma_bf16(float* c, const uint32_t* a, uint32_t b0, uint32_t b1) {
    asm volatile("mma.sync.aligned.m16n8k16.row.col.f32.bf16.bf16.f32 "
                 "{%0,%1,%2,%3}, {%4,%5,%6,%7}, {%8,%9}, {%0,%1,%2,%3};"
                 : "+f"(c[0]), "+f"(c[1]), "+f"(c[2]), "+f"(c[3])
                 : "r"(a[0]), "r"(a[1]), "r"(a[2]), "r"(a[3]), "r"(b0), "r"(b1));
}
__device__ __forceinline__ uint32_t pack_bf16_rn(float lo, float hi) {
    uint32_t r;
    asm("cvt.rn.bf16x2.f32 %0, %1, %2;" : "=r"(r) : "f"(hi), "f"(lo));
    return r;
}
__device__ __forceinline__ uint32_t split2(float2 v, uint32_t& lo) {
    uint32_t hx = (__float_as_uint(v.x) + 0x8000u) & 0xFFFF0000u;
    uint32_t hy = (__float_as_uint(v.y) + 0x8000u) & 0xFFFF0000u;
    lo = pack_bf16_rn(v.x - __uint_as_float(hx), v.y - __uint_as_float(hy));
    return __byte_perm(hx, hy, 0x7632);
}
__device__ __forceinline__ void split_g(float v, __nv_bfloat16* ph, __nv_bfloat16* pl) {
    __nv_bfloat16 h = __float2bfloat16(v);
    *ph = h;
    *pl = __float2bfloat16(v - __bfloat162float(h));
}

// ---------- prep: split((features @ W)^T) -> g_bh1/g_bl1 ----------
__global__ void feat_w_kernel(const float* __restrict__ feat,
                              const float* __restrict__ W) {
    __shared__ float sW[F_DIM * F_DIM];
    int tid = threadIdx.x;
    for (int i = tid; i < F_DIM * F_DIM; i += 128) sW[i] = W[i];
    __syncthreads();
    int row = blockIdx.x * 128 + tid;
    float f[F_DIM];
    const float4* fr = reinterpret_cast<const float4*>(feat + (size_t)row * F_DIM);
#pragma unroll
    for (int i = 0; i < 8; i++) {
        float4 v = fr[i];
        f[4*i] = v.x; f[4*i+1] = v.y; f[4*i+2] = v.z; f[4*i+3] = v.w;
    }
#pragma unroll 4
    for (int c = 0; c < F_DIM; c++) {
        float acc = 0.f;
#pragma unroll
        for (int k = 0; k < F_DIM; k++) acc = fmaf(f[k], sW[k * F_DIM + c], acc);
        split_g(acc, &g_bh1[(size_t)c * N_DIM + row], &g_bl1[(size_t)c * N_DIM + row]);
    }
}

// ---------- persistent big GEMM: partials over K-chunks ----------
// MODE 1: B = g_bh1/g_bl1 ; MODE 2: B = g_bh2/g_bl2
template <int MODE>
__global__ __launch_bounds__(THREADS, 1)
void big_gemm_mma(const float* __restrict__ A) {
    const __nv_bfloat16* __restrict__ Bh = (MODE == 1) ? g_bh1 : g_bh2;
    const __nv_bfloat16* __restrict__ Bl = (MODE == 1) ? g_bl1 : g_bl2;

    extern __shared__ char smem[];
    const uint32_t sb = smem_u32(smem);
    const int tid  = threadIdx.x;
    const int lane = tid & 31;
    const int w    = tid >> 5;

    const int u0 = (blockIdx.x * TOTAL_UNITS) / GRID;
    const int u1 = ((blockIdx.x + 1) * TOTAL_UNITS) / GRID;
    const int S0 = u0 * UNIT_STAGES;
    const int S1 = u1 * UNIT_STAGES;

    // ---- producer slots ----
    int arow[8]; int agr[8]; uint32_t adst[8];
#pragma unroll
    for (int i = 0; i < 8; i++) {
        int chunk = tid + THREADS * i;
        arow[i] = chunk >> 4;  agr[i] = chunk & 15;
        adst[i] = (uint32_t)(arow[i] * 256 + ((agr[i] ^ (arow[i] & 7)) << 4));
    }
    const int bn = tid >> 3, bg = tid & 7;
    const uint32_t bdst = (uint32_t)(STAGE_A_SZ + bn * ROWB + bg * 16);

    auto issue = [&](int s) {
        const int u = s >> 5;
        const int m = u >> 3;
        const int kf = ((u & 7) * UNIT_STAGES + (s & 31)) * BK;   // absolute k (floats)
        const uint32_t stg = sb + (s & 3) * STAGE_SZ;
        const float* abase = A + (size_t)(m * BM) * N_DIM + kf;
#pragma unroll
        for (int i = 0; i < 8; i++)
            CP_ASYNC16(stg + adst[i], abase + (size_t)arow[i] * N_DIM + agr[i] * 4);
        const __nv_bfloat16* bh = Bh + (size_t)bn * N_DIM + kf + bg * 8;
        const __nv_bfloat16* bl = Bl + (size_t)bn * N_DIM + kf + bg * 8;
        CP_ASYNC16(stg + bdst, bh);
        CP_ASYNC16(stg + bdst + BH_SZ, bl);
    };

    // ---- consumer addressing ----
    const int r1 = w * 16 + (lane >> 2);
    const uint32_t xr = (uint32_t)(r1 & 7);
    const uint32_t arow1 = (uint32_t)(r1 * 256);
    const uint32_t arow2 = arow1 + 8 * 256;
    const uint32_t gb  = (uint32_t)((lane & 3) >> 1);
    const uint32_t aib = (uint32_t)((lane & 1) * 8);
    const uint32_t boff = (uint32_t)(STAGE_A_SZ + (lane >> 2) * ROWB + (lane & 3) * 4);

    float acc[4][4];
#pragma unroll
    for (int j = 0; j < 4; j++)
#pragma unroll
        for (int i = 0; i < 4; i++) acc[j][i] = 0.f;

    issue(S0);     CP_COMMIT();
    issue(S0 + 1); CP_COMMIT();
    issue(S0 + 2); CP_COMMIT();

    for (int s = S0; s < S1; s++) {
        CP_WAIT2();
        __syncthreads();
        if (s + 3 < S1) issue(s + 3);
        CP_COMMIT();

        const uint32_t stg = sb + (s & 3) * STAGE_SZ;
#pragma unroll
        for (int kk = 0; kk < 4; kk++) {
            const uint32_t g0 = gb + (uint32_t)(kk * 4);
            const uint32_t g2 = g0 + 2;
            float2 v0 = lds_f2(stg + arow1 + ((g0 ^ xr) << 4) + aib);
            float2 v1 = lds_f2(stg + arow2 + ((g0 ^ xr) << 4) + aib);
            float2 v2 = lds_f2(stg + arow1 + ((g2 ^ xr) << 4) + aib);
            float2 v3 = lds_f2(stg + arow2 + ((g2 ^ xr) << 4) + aib);
            uint32_t ah[4], al[4];
            ah[0] = split2(v0, al[0]);
            ah[1] = split2(v1, al[1]);
            ah[2] = split2(v2, al[2]);
            ah[3] = split2(v3, al[3]);
            const uint32_t bH = stg + boff + (uint32_t)(kk * 32);
#pragma unroll
            for (int j = 0; j < 4; j++) {
                const uint32_t bo = bH + (uint32_t)(j * 8 * ROWB);
                uint32_t bh0 = lds32(bo);
                uint32_t bh1 = lds32(bo + 16);
                uint32_t bl0 = lds32(bo + BH_SZ);
                uint32_t bl1 = lds32(bo + BH_SZ + 16);
                mma_bf16(acc[j], ah, bh0, bh1);
                mma_bf16(acc[j], al, bh0, bh1);
                mma_bf16(acc[j], ah, bl0, bl1);
            }
        }

        if ((s & 31) == 31) {      // unit complete -> flush partials
            const int u = s >> 5;
            const int m = u >> 3, kc = u & 7;
            float* pp = g_part + ((size_t)kc << 19);
            const int gr0 = m * BM + w * 16 + (lane >> 2);
            const int gr1 = gr0 + 8;
#pragma unroll
            for (int j = 0; j < 4; j++) {
                const int c = j * 8 + (lane & 3) * 2;
                *reinterpret_cast<float2*>(pp + (size_t)gr0 * F_DIM + c) =
                    make_float2(acc[j][0], acc[j][1]);
                *reinterpret_cast<float2*>(pp + (size_t)gr1 * F_DIM + c) =
                    make_float2(acc[j][2], acc[j][3]);
                acc[j][0] = acc[j][1] = acc[j][2] = acc[j][3] = 0.f;
            }
        }
    }
}

// ---------- reduce partials -> diag scale -> split -> g_bh2/g_bl2 (transposed) ----------
__global__ void reduce_split_kernel(const float* __restrict__ diag) {
    __shared__ unsigned short sh[F_DIM][33], sl[F_DIM][33];
    const int tid = threadIdx.x;
    const int r0 = blockIdx.x * 32;
    const int rl = tid >> 3;          // 0..31 local row
    const int c4 = (tid & 7) * 4;     // col base
    const int r = r0 + rl;
    float4 acc = *reinterpret_cast<const float4*>(g_part + (size_t)r * F_DIM + c4);
#pragma unroll
    for (int kc = 1; kc < KCHUNKS; kc++) {
        float4 v = *reinterpret_cast<const float4*>(
            g_part + ((size_t)kc << 19) + (size_t)r * F_DIM + c4);
        acc.x += v.x; acc.y += v.y; acc.z += v.z; acc.w += v.w;
    }
    const float d = diag[r];
    float vv[4] = {acc.x * d, acc.y * d, acc.z * d, acc.w * d};
#pragma unroll
    for (int i = 0; i < 4; i++) {
        __nv_bfloat16 h = __float2bfloat16(vv[i]);
        __nv_bfloat16 l = __float2bfloat16(vv[i] - __bfloat162float(h));
        sh[c4 + i][rl] = __bfloat16_as_ushort(h);
        sl[c4 + i][rl] = __bfloat16_as_ushort(l);
    }
    __syncthreads();
    // write transposed: thread -> c = tid>>3, 4 consecutive r
    const int cc = tid >> 3;
    const int rr = (tid & 7) * 4;
    ushort4 oh = make_ushort4(sh[cc][rr], sh[cc][rr+1], sh[cc][rr+2], sh[cc][rr+3]);
    ushort4 ol = make_ushort4(sl[cc][rr], sl[cc][rr+1], sl[cc][rr+2], sl[cc][rr+3]);
    *reinterpret_cast<ushort4*>(&g_bh2[(size_t)cc * N_DIM + r0 + rr]) = oh;
    *reinterpret_cast<ushort4*>(&g_bl2[(size_t)cc * N_DIM + r0 + rr]) = ol;
}

// ---------- reduce partials -> f32 out ----------
__global__ void reduce_out_kernel(float* __restrict__ out) {
    const int idx = blockIdx.x * blockDim.x + threadIdx.x;   // float4 index
    float4 acc = *reinterpret_cast<const float4*>(g_part + (size_t)idx * 4);
#pragma unroll
    for (int kc = 1; kc < KCHUNKS; kc++) {
        float4 v = *reinterpret_cast<const float4*>(
            g_part + ((size_t)kc << 19) + (size_t)idx * 4);
        acc.x += v.x; acc.y += v.y; acc.z += v.z; acc.w += v.w;
    }
    *reinterpret_cast<float4*>(out + (size_t)idx * 4) = acc;
}

extern "C" void kernel_launch(void* const* d_in, const int* in_sizes, int n_in,
                              void* d_out, int out_size) {
    const float* feat = (const float*)d_in[0];  // [16384, 32]
    const float* wav  = (const float*)d_in[1];  // [16384, 16384]
    const float* wavi = (const float*)d_in[2];  // [16384, 16384]
    const float* diag = (const float*)d_in[3];  // [16384]
    const float* Wm   = (const float*)d_in[4];  // [32, 32]
    float* out = (float*)d_out;

    cudaFuncSetAttribute(big_gemm_mma<1>, cudaFuncAttributeMaxDynamicSharedMemorySize, SMEM_TOTAL);
    cudaFuncSetAttribute(big_gemm_mma<2>, cudaFuncAttributeMaxDynamicSharedMemorySize, SMEM_TOTAL);

    feat_w_kernel<<<N_DIM / 128, 128>>>(feat, Wm);
    big_gemm_mma<1><<<GRID, THREADS, SMEM_TOTAL>>>(wavi);
    reduce_split_kernel<<<N_DIM / 32, 256>>>(diag);
    big_gemm_mma<2><<<GRID, THREADS, SMEM_TOTAL>>>(wav);
    reduce_out_kernel<<<(N_DIM * F_DIM / 4) / 256, 256>>>(out);
}